// round 3
// baseline (speedup 1.0000x reference)
#include <cuda_runtime.h>

#define TWO_PI_F 6.283185307179586f
#define NROT 8
#define C_DIM 128
#define KS 5
#define PATCH 25
#define TPB 512
#define CIN_CHUNK 64
#define CIN_CHUNKS 2
#define CI_PAD 65                 // smem ci-stride (banks: 65 % 32 = 1, conflict-free)
#define SMEM_FLOATS 13000         // max(8*25*65, 64*201) = max(13000, 12864)
#define SMEM_BYTES (SMEM_FLOATS * 4)

__global__ __launch_bounds__(TPB)
void gk_reg_kernel(const float* __restrict__ in_H,
                   const float* __restrict__ out_H,
                   const float* __restrict__ weight,
                   float* __restrict__ out)
{
    extern __shared__ float sbuf[];

    const int co      = blockIdx.x;
    const int o       = blockIdx.y;
    const int ci_base = blockIdx.z * CIN_CHUNK;
    const int tid     = threadIdx.x;

    // ---- phase 1: load weight slab [g][ci64][q25] -> smem [g][q][ci] (pad 65) ----
    // gmem: weight[((g*128+co)*128 + ci)*25 + q], contiguous in e = g*1600 + ci*25 + q
#pragma unroll
    for (int k = 0; k < 25; ++k) {
        int e  = tid + k * TPB;            // 0..12799
        int g  = e / 1600;
        int r  = e - g * 1600;
        int ci = r / 25;
        int q  = r - ci * 25;
        float v = weight[((size_t)(g * C_DIM + co) * C_DIM + (ci_base + ci)) * PATCH + q];
        sbuf[(g * PATCH + q) * CI_PAD + ci] = v;   // STS: consecutive e -> stride-65 addrs, conflict-free
    }

    // ---- per-thread (i, ci_local) ----
    const int i   = tid >> 6;          // 0..7
    const int cil = tid & 63;          // 0..63

    const float outH  = out_H[o];
    const float theta = in_H[i] - outH;
    const float tmod  = theta - floorf(theta * (1.0f / TWO_PI_F)) * TWO_PI_F;
    const float pos   = tmod * ((float)NROT / TWO_PI_F);
    const float fl    = floorf(pos);
    int g0 = ((int)fl) % NROT;
    if (g0 >= NROT) g0 -= NROT;
    const int g1 = (g0 + 1) & (NROT - 1);
    const float frac = pos - fl;

    const float cc = cosf(-outH), ss = sinf(-outH);

    __syncthreads();

    const float* s0 = sbuf + g0 * (PATCH * CI_PAD) + cil;
    const float* s1 = sbuf + g1 * (PATCH * CI_PAD) + cil;

    float acc[PATCH];

#pragma unroll
    for (int p = 0; p < PATCH; ++p) {
        const int px = p % KS, py = p / KS;
        const float X = -1.0f + 0.5f * (float)px;     // exact linspace(-1,1,5)
        const float Y = -1.0f + 0.5f * (float)py;
        if (X * X + Y * Y > 1.000001f) {              // compile-time mask prune
            acc[p] = 0.0f;
            continue;
        }
        const float gx = cc * X - ss * Y;
        const float gy = ss * X + cc * Y;
        const float sx = fmaf(gx, 2.0f, 2.0f);        // (gx+1)*0.5*(KS-1)
        const float sy = fmaf(gy, 2.0f, 2.0f);
        const float fxf = floorf(sx), fyf = floorf(sy);
        const float fx = sx - fxf, fy = sy - fyf;
        int x0 = min(max((int)fxf, 0), KS - 1);
        int y0 = min(max((int)fyf, 0), KS - 1);
        const int x1 = min(x0 + 1, KS - 1);
        const int y1 = min(y0 + 1, KS - 1);

        const int q00 = (y0 * KS + x0) * CI_PAD;
        const int q01 = (y0 * KS + x1) * CI_PAD;
        const int q10 = (y1 * KS + x0) * CI_PAD;
        const int q11 = (y1 * KS + x1) * CI_PAD;

        // Gk lerp per corner, then bilinear lerp (mask == 1 for active p)
        const float a00 = s0[q00], b00 = s1[q00];
        const float a01 = s0[q01], b01 = s1[q01];
        const float a10 = s0[q10], b10 = s1[q10];
        const float a11 = s0[q11], b11 = s1[q11];
        const float v00 = fmaf(frac, b00 - a00, a00);
        const float v01 = fmaf(frac, b01 - a01, a01);
        const float v10 = fmaf(frac, b10 - a10, a10);
        const float v11 = fmaf(frac, b11 - a11, a11);
        const float top = fmaf(fx, v01 - v00, v00);
        const float bot = fmaf(fx, v11 - v10, v10);
        acc[p] = fmaf(fy, bot - top, top);
    }

    // ---- phase 3: stage to smem (reuse buffer), then coalesced copy out ----
    __syncthreads();   // all weight reads done before overwrite

    // stage layout: [ci64][r200] with row stride 201 (bank-safe: lanes stride 201 -> distinct)
#pragma unroll
    for (int p = 0; p < PATCH; ++p)
        sbuf[cil * 201 + i * PATCH + p] = acc[p];

    __syncthreads();

    // out[ci][o][co][i][p] = ci*204800 + (o*128+co)*200 + r
    float* obase = out + (size_t)ci_base * (NROT * C_DIM * 200)
                       + (size_t)(o * C_DIM + co) * 200;
#pragma unroll
    for (int k = 0; k < 25; ++k) {
        int e  = tid + k * TPB;            // 0..12799
        int ci = e / 200;
        int r  = e - ci * 200;
        obase[(size_t)ci * (NROT * C_DIM * 200) + r] = sbuf[ci * 201 + r];
    }
}

extern "C" void kernel_launch(void* const* d_in, const int* in_sizes, int n_in,
                              void* d_out, int out_size)
{
    const float* in_H   = (const float*)d_in[0];
    const float* out_H  = (const float*)d_in[1];
    const float* weight = (const float*)d_in[2];
    float* out = (float*)d_out;

    cudaFuncSetAttribute(gk_reg_kernel,
                         cudaFuncAttributeMaxDynamicSharedMemorySize, SMEM_BYTES);

    dim3 grid(C_DIM, NROT, CIN_CHUNKS);   // (cout, o, ci chunks of 64)
    gk_reg_kernel<<<grid, TPB, SMEM_BYTES>>>(in_H, out_H, weight, out);
}

// round 4
// speedup vs baseline: 1.2147x; 1.2147x over previous
#include <cuda_runtime.h>

#define TWO_PI_F 6.283185307179586f
#define NROT 8
#define C_DIM 128
#define KS 5
#define PATCH 25
#define TPB 256
#define CIN_CHUNK 32
#define CIN_CHUNKS 4

// smem float offsets
#define SLAB_OFF   0        // [g8][ci32][q25] = 6400 floats
#define STAGE_OFF  6400     // [r200][ci] stride 33 = 6600 floats
#define CTAB_OFF   13000    // 200 * 8 floats (two float4 per (i,p)) = 1600
#define QTAB_OFF   14600    // 25 * int4 = 100
#define SMEM_FLOATS 14700
#define SMEM_BYTES (SMEM_FLOATS * 4)

#define OUT_CI_STRIDE (NROT * C_DIM * 200)   // 204800

__global__ __launch_bounds__(TPB)
void gk_tab_kernel(const float* __restrict__ in_H,
                   const float* __restrict__ out_H,
                   const float* __restrict__ weight,
                   float* __restrict__ out)
{
    extern __shared__ float sbuf[];
    float* slab  = sbuf + SLAB_OFF;
    float* stage = sbuf + STAGE_OFF;
    float4* ctab = (float4*)(sbuf + CTAB_OFF);   // ctab[(i*25+p)*2 + {0,1}]
    int4*   qtab = (int4*)(sbuf + QTAB_OFF);

    const int co      = blockIdx.x;
    const int o       = blockIdx.y;
    const int ci_base = blockIdx.z * CIN_CHUNK;
    const int tid     = threadIdx.x;
    const int w       = tid >> 5;       // warp = i
    const int lane    = tid & 31;       // lane = ci (local)

    const float outH = out_H[o];

    // ---------------- phase 1a: fill slab (pure float4 copy, no div/mod) ----------------
    // gmem per g: 800 contiguous floats at ((g*128+co)*128+ci_base)*25
    {
        const float4* __restrict__ w4 = (const float4*)weight;
#pragma unroll
        for (int g = 0; g < NROT; ++g) {
            if (tid < 200) {
                size_t gb4 = ((size_t)((g * C_DIM + co) * C_DIM + ci_base) * PATCH) >> 2;
                float4 v = w4[gb4 + tid];
                *(float4*)&slab[g * 800 + tid * 4] = v;
            }
        }
    }

    // ---------------- phase 1b: build coefficient tables ----------------
    if (tid < 200) {
        const int ti = tid / 25;
        const int tp = tid - ti * 25;

        // per-i Gk lerp
        const float theta = in_H[ti] - outH;
        const float tmod  = theta - floorf(theta * (1.0f / TWO_PI_F)) * TWO_PI_F;
        const float pos   = tmod * ((float)NROT / TWO_PI_F);
        const float fl    = floorf(pos);
        const float frac  = pos - fl;

        // per-p bilinear (block-uniform in o)
        const int px = tp % KS, py = tp / KS;
        const float X = -1.0f + 0.5f * (float)px;
        const float Y = -1.0f + 0.5f * (float)py;
        const float cc = cosf(-outH), ss = sinf(-outH);
        const float gx = cc * X - ss * Y;
        const float gy = ss * X + cc * Y;
        const float sx = fmaf(gx, 2.0f, 2.0f);
        const float sy = fmaf(gy, 2.0f, 2.0f);
        const float fxf = floorf(sx), fyf = floorf(sy);
        const float fx = sx - fxf, fy = sy - fyf;
        int x0 = min(max((int)fxf, 0), KS - 1);
        int y0 = min(max((int)fyf, 0), KS - 1);
        const int x1 = min(x0 + 1, KS - 1);
        const int y1 = min(y0 + 1, KS - 1);

        const float w00 = (1.0f - fy) * (1.0f - fx);
        const float w01 = (1.0f - fy) * fx;
        const float w10 = fy * (1.0f - fx);
        const float w11 = fy * fx;
        const float a = 1.0f - frac;

        ctab[tid * 2 + 0] = make_float4(w00 * a, w01 * a, w10 * a, w11 * a);
        ctab[tid * 2 + 1] = make_float4(w00 * frac, w01 * frac, w10 * frac, w11 * frac);

        if (ti == 0)
            qtab[tp] = make_int4(y0 * KS + x0, y0 * KS + x1,
                                 y1 * KS + x0, y1 * KS + x1);
    }

    // per-thread (warp-uniform) g0/g1 for i = w
    const float theta = in_H[w] - outH;
    const float tmod  = theta - floorf(theta * (1.0f / TWO_PI_F)) * TWO_PI_F;
    const float pos   = tmod * ((float)NROT / TWO_PI_F);
    int g0 = ((int)floorf(pos)) % NROT;
    if (g0 >= NROT) g0 -= NROT;
    const int g1 = (g0 + 1) & (NROT - 1);

    __syncthreads();

    // ---------------- phase 2: compute into stage ----------------
    // slab[(g*32+ci)*25 + q]; lanes (ci) stride 25 -> conflict-free
    const float* base0 = slab + (g0 * CIN_CHUNK + lane) * PATCH;
    const float* base1 = slab + (g1 * CIN_CHUNK + lane) * PATCH;
    const int crow = w * PATCH;   // i*25

#pragma unroll
    for (int p = 0; p < PATCH; ++p) {
        const int px = p % KS, py = p / KS;
        const float Xc = -1.0f + 0.5f * (float)px;
        const float Yc = -1.0f + 0.5f * (float)py;
        float* st = &stage[(crow + p) * 33 + lane];  // lanes consecutive: conflict-free
        if (Xc * Xc + Yc * Yc > 1.000001f) {
            *st = 0.0f;                               // masked tap: exact zero
        } else {
            const int4   q  = qtab[p];                // broadcast LDS
            const float4 ca = ctab[(crow + p) * 2 + 0];
            const float4 cb = ctab[(crow + p) * 2 + 1];
            float v;
            v  = ca.x * base0[q.x];
            v  = fmaf(ca.y, base0[q.y], v);
            v  = fmaf(ca.z, base0[q.z], v);
            v  = fmaf(ca.w, base0[q.w], v);
            v  = fmaf(cb.x, base1[q.x], v);
            v  = fmaf(cb.y, base1[q.y], v);
            v  = fmaf(cb.z, base1[q.z], v);
            v  = fmaf(cb.w, base1[q.w], v);
            *st = v;
        }
    }

    __syncthreads();

    // ---------------- phase 3: coalesced copy out ----------------
    // out[ci][o][co][r], r = i*25+p in [0,200); ci row contiguous
    float* obase = out + (size_t)ci_base * OUT_CI_STRIDE
                       + (size_t)(o * C_DIM + co) * 200;
#pragma unroll
    for (int cj = 0; cj < 4; ++cj) {
        const int ci = w + cj * 8;
        float* orow = obase + (size_t)ci * OUT_CI_STRIDE;
        const float* srow = stage + ci;
#pragma unroll
        for (int it = 0; it < 2; ++it) {
            const int f4 = lane + it * 32;
            if (f4 < 50) {
                const int r = f4 * 4;
                float4 v;
                v.x = srow[(r + 0) * 33];   // lanes stride 4*33 -> banks stride 4, distinct
                v.y = srow[(r + 1) * 33];
                v.z = srow[(r + 2) * 33];
                v.w = srow[(r + 3) * 33];
                *(float4*)(orow + r) = v;
            }
        }
    }
}

extern "C" void kernel_launch(void* const* d_in, const int* in_sizes, int n_in,
                              void* d_out, int out_size)
{
    const float* in_H   = (const float*)d_in[0];
    const float* out_H  = (const float*)d_in[1];
    const float* weight = (const float*)d_in[2];
    float* out = (float*)d_out;

    cudaFuncSetAttribute(gk_tab_kernel,
                         cudaFuncAttributeMaxDynamicSharedMemorySize, SMEM_BYTES);

    dim3 grid(C_DIM, NROT, CIN_CHUNKS);   // (cout, o, ci chunks of 32)
    gk_tab_kernel<<<grid, TPB, SMEM_BYTES>>>(in_H, out_H, weight, out);
}

// round 5
// speedup vs baseline: 1.5311x; 1.2604x over previous
#include <cuda_runtime.h>

#define TWO_PI_F 6.283185307179586f
#define NROT 8
#define C_DIM 128
#define KS 5
#define PATCH 25
#define TPB 256
#define CIN_CHUNK 32
#define CIN_CHUNKS 4
#define NACT 13
#define ACT_MASK 0x477DC4u          // bit p set iff X^2+Y^2 <= 1 on the 5x5 grid

#define OUT_CI_STRIDE (NROT * C_DIM * 200)   // 204800

// smem float layout:
//   [0, 6432)        : slab [g8][ci32][q25] (phase A)  / stage [ci32][r201] (phase B+, aliased)
//   [6432, 9760)     : wbil [g8][pa13][ci32]  (pad-free: lane=ci consecutive)
//   [9760, 9812)     : ctab float4[13]
//   [9812, 9864)     : qtab int4[13]
#define SLAB_OFF  0
#define STAGE_OFF 0
#define WBIL_OFF  6432
#define CTAB_OFF  9760
#define QTAB_OFF  9812
#define SMEM_FLOATS 9864

__device__ __constant__ int APLIST[NACT] = {2,6,7,8,10,11,12,13,14,16,17,18,22};

__global__ __launch_bounds__(TPB)
void gk_factored_kernel(const float* __restrict__ in_H,
                        const float* __restrict__ out_H,
                        const float* __restrict__ weight,
                        float* __restrict__ out)
{
    __shared__ float sbuf[SMEM_FLOATS];
    float*  slab  = sbuf + SLAB_OFF;
    float*  stage = sbuf + STAGE_OFF;
    float*  wbil  = sbuf + WBIL_OFF;
    float4* ctab  = (float4*)(sbuf + CTAB_OFF);
    int4*   qtab  = (int4*)(sbuf + QTAB_OFF);

    const int co      = blockIdx.x;
    const int o       = blockIdx.y;
    const int ci_base = blockIdx.z * CIN_CHUNK;
    const int tid     = threadIdx.x;
    const int w       = tid >> 5;     // warp id: used as g (phase A) and i (phase B)
    const int lane    = tid & 31;     // lane = ci

    const float outH = out_H[o];

    // ---- phase 0a: fill slab via float4 copy (layout identical to gmem per-g) ----
    {
        const float4* __restrict__ w4 = (const float4*)weight;
#pragma unroll
        for (int k = 0; k < 7; ++k) {
            int f = tid + k * TPB;                  // float4 index, 0..1599
            if (f < 1600) {
                int g = f / 200;
                int r = f - g * 200;
                size_t gb4 = ((size_t)((g * C_DIM + co) * C_DIM + ci_base) * PATCH) >> 2;
                *(float4*)&slab[g * 800 + r * 4] = w4[gb4 + r];
            }
        }
    }

    // ---- phase 0b: bilinear coefficient tables for the 13 active taps ----
    if (tid < NACT) {
        const int p  = APLIST[tid];
        const int px = p % KS, py = p / KS;
        const float X = -1.0f + 0.5f * (float)px;
        const float Y = -1.0f + 0.5f * (float)py;
        const float cc = cosf(-outH), ss = sinf(-outH);
        const float gx = cc * X - ss * Y;
        const float gy = ss * X + cc * Y;
        const float sx = fmaf(gx, 2.0f, 2.0f);
        const float sy = fmaf(gy, 2.0f, 2.0f);
        const float fxf = floorf(sx), fyf = floorf(sy);
        const float fx = sx - fxf, fy = sy - fyf;
        int x0 = min(max((int)fxf, 0), KS - 1);
        int y0 = min(max((int)fyf, 0), KS - 1);
        const int x1 = min(x0 + 1, KS - 1);
        const int y1 = min(y0 + 1, KS - 1);
        ctab[tid] = make_float4((1.0f - fy) * (1.0f - fx), (1.0f - fy) * fx,
                                fy * (1.0f - fx),          fy * fx);
        qtab[tid] = make_int4(y0 * KS + x0, y0 * KS + x1,
                              y1 * KS + x0, y1 * KS + x1);
    }

    // per-warp Gk lerp params for i = w (used in phase B)
    const float theta = in_H[w] - outH;
    const float tmod  = theta - floorf(theta * (1.0f / TWO_PI_F)) * TWO_PI_F;
    const float pos   = tmod * ((float)NROT / TWO_PI_F);
    int g0 = ((int)floorf(pos)) % NROT;
    if (g0 >= NROT) g0 -= NROT;
    const int g1 = (g0 + 1) & (NROT - 1);
    const float frac = pos - floorf(pos);

    __syncthreads();

    // ---- phase A: bilinear gather once per g-slab: wbil[g][pa][ci] ----
    // warp w handles g = w; lane = ci (stride 25 in slab -> conflict-free)
    {
        const float* srow = slab + w * 800 + lane * PATCH;
#pragma unroll
        for (int pa = 0; pa < NACT; ++pa) {
            const int4   q = qtab[pa];      // broadcast
            const float4 c = ctab[pa];      // broadcast
            float v;
            v = c.x * srow[q.x];
            v = fmaf(c.y, srow[q.y], v);
            v = fmaf(c.z, srow[q.z], v);
            v = fmaf(c.w, srow[q.w], v);
            wbil[(w * NACT + pa) * 32 + lane] = v;   // lanes consecutive
        }
    }

    __syncthreads();   // slab dead; stage may now overwrite it

    // ---- phase B: 2-point Gk lerp into stage[ci][r] (pad 201, conflict-free) ----
    {
        const float* b0 = wbil + g0 * (NACT * 32) + lane;
        const float* b1 = wbil + g1 * (NACT * 32) + lane;
#pragma unroll
        for (int pa = 0; pa < NACT; ++pa) {
            const float v0 = b0[pa * 32];
            const float v1 = b1[pa * 32];
            const int   r  = w * PATCH + APLIST[pa];
            stage[lane * 201 + r] = fmaf(frac, v1 - v0, v0);
        }
    }

    __syncthreads();

    // ---- phase C: transpose copy-out; masked taps emit literal 0 ----
    // warp w writes rows ci = w, w+8, w+16, w+24; lane = r-chunk (consecutive)
    float* obase = out + (size_t)ci_base * OUT_CI_STRIDE
                       + (size_t)(o * C_DIM + co) * 200;
#pragma unroll
    for (int cj = 0; cj < 4; ++cj) {
        const int ci = w + cj * 8;
        const float* srow = stage + ci * 201;
        float* orow = obase + (size_t)ci * OUT_CI_STRIDE;
#pragma unroll
        for (int rc = 0; rc < 7; ++rc) {
            const int r = rc * 32 + lane;
            if (r < 200) {
                const int p = r % PATCH;
                const float v = ((ACT_MASK >> p) & 1u) ? srow[r] : 0.0f;
                orow[r] = v;
            }
        }
    }
}

extern "C" void kernel_launch(void* const* d_in, const int* in_sizes, int n_in,
                              void* d_out, int out_size)
{
    const float* in_H   = (const float*)d_in[0];
    const float* out_H  = (const float*)d_in[1];
    const float* weight = (const float*)d_in[2];
    float* out = (float*)d_out;

    dim3 grid(C_DIM, NROT, CIN_CHUNKS);   // (cout, o, ci chunks of 32)
    gk_factored_kernel<<<grid, TPB>>>(in_H, out_H, weight, out);
}

// round 6
// speedup vs baseline: 1.7828x; 1.1644x over previous
#include <cuda_runtime.h>

#define TWO_PI_F 6.283185307179586f
#define NROT 8
#define C_DIM 128
#define KS 5
#define PATCH 25
#define TPB 256
#define CIN_CHUNK 32
#define NACT 13
#define OGRP 4                      // o's per block
#define ACT_MASK 0x477DC4u         // bit p set iff X^2+Y^2 <= 1 on the 5x5 grid
#define OUT_CI_STRIDE (NROT * C_DIM * 200)   // 204800
#define WPAD 105                    // wbil row stride (105 % 32 = 9, conflict-free)

__device__ __constant__ int APLIST[NACT] = {2,6,7,8,10,11,12,13,14,16,17,18,22};

__global__ __launch_bounds__(TPB)
void gk_ofused_kernel(const float* __restrict__ in_H,
                      const float* __restrict__ out_H,
                      const float* __restrict__ weight,
                      float* __restrict__ out)
{
    __shared__ float  slab[NROT * 800];        // [g][ci32][q25] 25.6 KB, live whole kernel
    __shared__ float  wbil[CIN_CHUNK * WPAD];  // [ci][g*13+pa]  13.4 KB
    __shared__ float  ftab[OGRP * 8];          // frac per (oo,i)
    __shared__ int    gtab[OGRP * 8];          // g0  per (oo,i)
    __shared__ float4 ctab[OGRP * NACT];
    __shared__ int4   qtab[OGRP * NACT];

    const int co      = blockIdx.x;
    const int ci_base = blockIdx.y * CIN_CHUNK;
    const int o_base  = blockIdx.z * OGRP;
    const int tid     = threadIdx.x;
    const int w       = tid >> 5;     // warp: g in phase A; ci-group in phase BC
    const int lane    = tid & 31;

    // ---- fill slab: pure float4 copy (per-g 800 contiguous floats) ----
    {
        const float4* __restrict__ w4 = (const float4*)weight;
#pragma unroll
        for (int k = 0; k < 7; ++k) {
            int f = tid + k * TPB;                    // float4 index 0..1599
            if (f < 1600) {
                int g = f / 200;
                int r = f - g * 200;
                size_t gb4 = ((size_t)((g * C_DIM + co) * C_DIM + ci_base) * PATCH) >> 2;
                *(float4*)&slab[g * 800 + r * 4] = w4[gb4 + r];
            }
        }
    }

    // ---- per-(oo,i) Gk lerp table ----
    if (tid < OGRP * 8) {
        const int oo = tid >> 3, i = tid & 7;
        const float outH  = out_H[o_base + oo];
        const float theta = in_H[i] - outH;
        const float tmod  = theta - floorf(theta * (1.0f / TWO_PI_F)) * TWO_PI_F;
        const float pos   = tmod * ((float)NROT / TWO_PI_F);
        int g0 = ((int)floorf(pos)) % NROT;
        if (g0 >= NROT) g0 -= NROT;
        ftab[tid] = pos - floorf(pos);
        gtab[tid] = g0;
    }

    // ---- per-(oo,pa) bilinear tables ----
    if (tid < OGRP * NACT) {
        const int oo = tid / NACT, pa = tid - oo * NACT;
        const int p  = APLIST[pa];
        const int px = p % KS, py = p / KS;
        const float X = -1.0f + 0.5f * (float)px;
        const float Y = -1.0f + 0.5f * (float)py;
        const float outH = out_H[o_base + oo];
        const float cc = cosf(-outH), ss = sinf(-outH);
        const float gx = cc * X - ss * Y;
        const float gy = ss * X + cc * Y;
        const float sx = fmaf(gx, 2.0f, 2.0f);
        const float sy = fmaf(gy, 2.0f, 2.0f);
        const float fxf = floorf(sx), fyf = floorf(sy);
        const float fx = sx - fxf, fy = sy - fyf;
        int x0 = min(max((int)fxf, 0), KS - 1);
        int y0 = min(max((int)fyf, 0), KS - 1);
        const int x1 = min(x0 + 1, KS - 1);
        const int y1 = min(y0 + 1, KS - 1);
        ctab[tid] = make_float4((1.0f - fy) * (1.0f - fx), (1.0f - fy) * fx,
                                fy * (1.0f - fx),          fy * fx);
        qtab[tid] = make_int4(y0 * KS + x0, y0 * KS + x1,
                              y1 * KS + x0, y1 * KS + x1);
    }

    // ---- per-lane loop-invariant r-chunk constants ----
    int i_rc[7], pa_rc[7];
    unsigned actm = 0;
#pragma unroll
    for (int rc = 0; rc < 7; ++rc) {
        const int r = rc * 32 + lane;
        const int ri = (r < 200) ? r : 0;
        const int ii = ri / 25;
        const int p  = ri - ii * 25;
        i_rc[rc]  = ii;
        pa_rc[rc] = __popc(ACT_MASK & ((1u << p) - 1u));
        if (r < 200 && ((ACT_MASK >> p) & 1u)) actm |= (1u << rc);
    }

    __syncthreads();

    for (int oo = 0; oo < OGRP; ++oo) {
        // ---- phase A: bilinear gather per g-slab -> wbil[ci][g*13+pa] ----
        {
            const float* srow = slab + w * 800 + lane * PATCH;   // lane=ci, stride 25: CF
            float* wrow = wbil + lane * WPAD + w * NACT;
#pragma unroll
            for (int pa = 0; pa < NACT; ++pa) {
                const int4   q = qtab[oo * NACT + pa];   // broadcast
                const float4 c = ctab[oo * NACT + pa];
                float v;
                v = c.x * srow[q.x];
                v = fmaf(c.y, srow[q.y], v);
                v = fmaf(c.z, srow[q.z], v);
                v = fmaf(c.w, srow[q.w], v);
                wrow[pa] = v;                            // lanes stride 105: CF
            }
        }
        __syncthreads();

        // ---- phase BC: Gk lerp + direct coalesced store ----
        float fr[7]; int off0[7], off1[7];
#pragma unroll
        for (int rc = 0; rc < 7; ++rc) {
            const int t = oo * 8 + i_rc[rc];
            fr[rc] = ftab[t];                            // <=2 distinct addrs/warp
            const int g0 = gtab[t];
            const int g1 = (g0 + 1) & (NROT - 1);
            off0[rc] = g0 * NACT + pa_rc[rc];
            off1[rc] = g1 * NACT + pa_rc[rc];
        }

        float* obase = out + (size_t)ci_base * OUT_CI_STRIDE
                           + (size_t)((o_base + oo) * C_DIM + co) * 200;
#pragma unroll
        for (int cj = 0; cj < 4; ++cj) {
            const int ci = w + cj * 8;
            const float* wrow = wbil + ci * WPAD;
            float* orow = obase + (size_t)ci * OUT_CI_STRIDE;
#pragma unroll
            for (int rc = 0; rc < 7; ++rc) {
                const int r = rc * 32 + lane;
                if (r < 200) {
                    float v = 0.0f;
                    if ((actm >> rc) & 1u) {
                        const float v0 = wrow[off0[rc]];
                        const float v1 = wrow[off1[rc]];
                        v = fmaf(fr[rc], v1 - v0, v0);
                    }
                    orow[r] = v;                         // lanes consecutive: coalesced
                }
            }
        }
        __syncthreads();   // wbil reused next oo
    }
}

extern "C" void kernel_launch(void* const* d_in, const int* in_sizes, int n_in,
                              void* d_out, int out_size)
{
    const float* in_H   = (const float*)d_in[0];
    const float* out_H  = (const float*)d_in[1];
    const float* weight = (const float*)d_in[2];
    float* out = (float*)d_out;

    dim3 grid(C_DIM, C_DIM / CIN_CHUNK, NROT / OGRP);   // (128, 4, 2) = 1024 blocks
    gk_ofused_kernel<<<grid, TPB>>>(in_H, out_H, weight, out);
}